// round 2
// baseline (speedup 1.0000x reference)
#include <cuda_runtime.h>
#include <math.h>

#define BB 32
#define SS 256
#define EE 300
#define EP 304
#define HH 256
#define T4H 1024
#define NT 19
#define TSTART 17
#define TSTOP 18

// ---------------- device scratch (no cudaMalloc allowed) ----------------
__device__ float    g_X[(size_t)BB * SS * EP];            // [n][e], n = t*32 + b
__device__ float    g_xg[(size_t)2 * SS * T4H * BB];      // [d][t][row][b]
__device__ float    g_h[(size_t)2 * SS * HH * BB];        // [d][t][k][b]
__device__ float    g_logits[(size_t)BB * SS * NT];       // [b][t][tag]
__device__ int      g_ptr[(size_t)BB * SS * NT];          // viterbi backpointers
__device__ float    g_nll[BB];
__device__ unsigned g_bar[SS];                            // per-step barrier counters

// ---------------- zero output + barrier counters ----------------
__global__ void zero_out_kernel(float* out, int n) {
    int i = blockIdx.x * blockDim.x + threadIdx.x;
    if (i < n) out[i] = 0.0f;
    if (i < SS) g_bar[i] = 0u;
}

// ---------------- embedding gather + mask -> padded X [8192][304] ----------------
__global__ void embed_kernel(const int* __restrict__ word, const int* __restrict__ mask,
                             const float* __restrict__ emb) {
    int idx = blockIdx.x * blockDim.x + threadIdx.x;
    int total = BB * SS * (EP / 4);
    if (idx >= total) return;
    int n = idx / (EP / 4), q = idx - n * (EP / 4);
    int t = n >> 5, b = n & 31;
    int w = word[b * SS + t];
    float m = (float)mask[b * SS + t];
    int e = q * 4;
    float4 v;
    if (e < EE) {
        float4 ev = *(const float4*)(emb + (size_t)w * EE + e);  // 300*4 and e*4 are 16B-aligned
        v.x = ev.x * m; v.y = ev.y * m; v.z = ev.z * m; v.w = ev.w * m;
    } else {
        v.x = v.y = v.z = v.w = 0.0f;
    }
    ((float4*)g_X)[(size_t)n * (EP / 4) + q] = v;
}

// ---------------- input-transform GEMM: xg[d][t][row][b] = X @ Wih_d.T + bih + bhh ----------------
__global__ __launch_bounds__(256) void gemm_xg_kernel(
    const float* __restrict__ WihF, const float* __restrict__ WihB,
    const float* __restrict__ bihF, const float* __restrict__ bhhF,
    const float* __restrict__ bihB, const float* __restrict__ bhhB) {
    __shared__ float As[16][64];
    __shared__ float Xs[16][68];
    int d = blockIdx.z;
    const float* Wih = d ? WihB : WihF;
    const float* bih = d ? bihB : bihF;
    const float* bhh = d ? bhhB : bhhF;
    int m0 = blockIdx.y * 64, n0 = blockIdx.x * 64;
    int tid = threadIdx.x;
    int lm = tid >> 2, kq = (tid & 3) * 4;
    int tx = tid & 15, ty = tid >> 4;
    float acc[4][4];
#pragma unroll
    for (int i = 0; i < 4; i++)
#pragma unroll
        for (int j = 0; j < 4; j++) acc[i][j] = 0.0f;

    for (int e0 = 0; e0 < EP; e0 += 16) {
        float4 a;
        if (e0 + kq < EE) {
            a = *(const float4*)(Wih + (size_t)(m0 + lm) * EE + e0 + kq);
        } else {
            a.x = a.y = a.z = a.w = 0.0f;
        }
        As[kq + 0][lm] = a.x; As[kq + 1][lm] = a.y; As[kq + 2][lm] = a.z; As[kq + 3][lm] = a.w;
        float4 xv = *(const float4*)(g_X + (size_t)(n0 + lm) * EP + e0 + kq);
        Xs[kq + 0][lm] = xv.x; Xs[kq + 1][lm] = xv.y; Xs[kq + 2][lm] = xv.z; Xs[kq + 3][lm] = xv.w;
        __syncthreads();
#pragma unroll
        for (int k = 0; k < 16; k++) {
            float4 av = *(const float4*)&As[k][ty * 4];
            float4 bv = *(const float4*)&Xs[k][tx * 4];
            acc[0][0] += av.x * bv.x; acc[0][1] += av.x * bv.y; acc[0][2] += av.x * bv.z; acc[0][3] += av.x * bv.w;
            acc[1][0] += av.y * bv.x; acc[1][1] += av.y * bv.y; acc[1][2] += av.y * bv.z; acc[1][3] += av.y * bv.w;
            acc[2][0] += av.z * bv.x; acc[2][1] += av.z * bv.y; acc[2][2] += av.z * bv.z; acc[2][3] += av.z * bv.w;
            acc[3][0] += av.w * bv.x; acc[3][1] += av.w * bv.y; acc[3][2] += av.w * bv.z; acc[3][3] += av.w * bv.w;
        }
        __syncthreads();
    }
#pragma unroll
    for (int i = 0; i < 4; i++) {
        int row = m0 + ty * 4 + i;
        float bias = bih[row] + bhh[row];
#pragma unroll
        for (int j = 0; j < 4; j++) {
            int n = n0 + tx * 4 + j;
            int tt = n >> 5, bb2 = n & 31;
            g_xg[(((size_t)d * SS + tt) * T4H + row) * BB + bb2] = acc[i][j] + bias;
        }
    }
}

// ---------------- persistent BiLSTM recurrence ----------------
// 128 blocks: bid>>6 = dir, bid&63 = slice m (4 hidden units -> 16 gate rows).
__global__ __launch_bounds__(128, 1) void lstm_kernel(
    const float* __restrict__ WhhF, const float* __restrict__ WhhB) {
    extern __shared__ float sm[];
    float* W_s  = sm;            // [256 k][16 r]
    float* h_s  = sm + 4096;     // [256 k][32 b]
    float* part = sm + 12288;    // [4 w][16 r][33 b]
    float* c_s  = sm + 14400;    // [4 u][32 b]

    int tid = threadIdx.x;
    int bid = blockIdx.x;
    int d = bid >> 6;
    int m = bid & 63;
    const float* Whh = d ? WhhB : WhhF;

    // stage Whh slice transposed: W_s[k*16 + r], r = gg*4+u -> gate row gg*256 + m*4 + u
    for (int i = tid; i < 4096; i += 128) {
        int r = i >> 8, k = i & 255;
        int gg = r >> 2, u = r & 3;
        W_s[k * 16 + r] = Whh[(size_t)(gg * HH + m * 4 + u) * HH + k];
    }
    c_s[tid] = 0.0f;
    __syncthreads();

    int lane = tid & 31, w = tid >> 5;
    int ggl = lane & 3, bg = lane >> 2;
    const float4* W4 = (const float4*)W_s;
    const float4* H4 = (const float4*)h_s;

    for (int it = 0; it < SS; it++) {
        int t = d ? (SS - 1 - it) : it;
        if (it > 0) {
            int tp = d ? t + 1 : t - 1;
            const float4* src = (const float4*)(g_h + (size_t)(d * SS + tp) * HH * BB);
            float4* dst = (float4*)h_s;
            for (int i = tid; i < 2048; i += 128) dst[i] = src[i];
        }
        __syncthreads();

        if (it > 0) {
            float a00=0,a01=0,a02=0,a03=0, a10=0,a11=0,a12=0,a13=0;
            float a20=0,a21=0,a22=0,a23=0, a30=0,a31=0,a32=0,a33=0;
            int k0 = w * 64;
#pragma unroll 8
            for (int k = k0; k < k0 + 64; k++) {
                float4 wv = W4[k * 4 + ggl];
                float4 hv = H4[k * 8 + bg];
                a00 += wv.x * hv.x; a01 += wv.x * hv.y; a02 += wv.x * hv.z; a03 += wv.x * hv.w;
                a10 += wv.y * hv.x; a11 += wv.y * hv.y; a12 += wv.y * hv.z; a13 += wv.y * hv.w;
                a20 += wv.z * hv.x; a21 += wv.z * hv.y; a22 += wv.z * hv.z; a23 += wv.z * hv.w;
                a30 += wv.w * hv.x; a31 += wv.w * hv.y; a32 += wv.w * hv.z; a33 += wv.w * hv.w;
            }
            int base = (w * 16 + ggl * 4) * 33 + bg * 4;
            part[base + 0*33 + 0] = a00; part[base + 0*33 + 1] = a01; part[base + 0*33 + 2] = a02; part[base + 0*33 + 3] = a03;
            part[base + 1*33 + 0] = a10; part[base + 1*33 + 1] = a11; part[base + 1*33 + 2] = a12; part[base + 1*33 + 3] = a13;
            part[base + 2*33 + 0] = a20; part[base + 2*33 + 1] = a21; part[base + 2*33 + 2] = a22; part[base + 2*33 + 3] = a23;
            part[base + 3*33 + 0] = a30; part[base + 3*33 + 1] = a31; part[base + 3*33 + 2] = a32; part[base + 3*33 + 3] = a33;
        }
        __syncthreads();

        // cell update: thread -> (u, b)
        {
            int u = tid >> 5, b = tid & 31;
            float g[4];
#pragma unroll
            for (int gg = 0; gg < 4; gg++) {
                float s = 0.0f;
                if (it > 0) {
                    int r = gg * 4 + u;
                    s = part[(0 * 16 + r) * 33 + b] + part[(1 * 16 + r) * 33 + b] +
                        part[(2 * 16 + r) * 33 + b] + part[(3 * 16 + r) * 33 + b];
                }
                s += g_xg[(((size_t)d * SS + t) * T4H + gg * HH + m * 4 + u) * BB + b];
                g[gg] = s;
            }
            float iv = 1.0f / (1.0f + expf(-g[0]));
            float fv = 1.0f / (1.0f + expf(-g[1]));
            float gv = tanhf(g[2]);
            float ov = 1.0f / (1.0f + expf(-g[3]));
            float c = fv * c_s[u * 32 + b] + iv * gv;
            c_s[u * 32 + b] = c;
            g_h[((size_t)(d * SS + t) * HH + m * 4 + u) * BB + b] = ov * tanhf(c);
        }
        __threadfence();
        __syncthreads();
        if (tid == 0) {
            atomicAdd(&g_bar[it], 1u);
            volatile unsigned* p = &g_bar[it];
            while (*p < 128u) __nanosleep(128);
        }
        __syncthreads();
    }
}

// ---------------- logits: [b][t][tag] = hcat . W_tag[tag] + b_tag ----------------
__global__ __launch_bounds__(256) void logits_kernel(const float* __restrict__ Wtag,
                                                     const float* __restrict__ btag) {
    extern __shared__ float hb[];  // [512 k][32 b]
    int t = blockIdx.x;
    int tid = threadIdx.x;
    for (int dd = 0; dd < 2; dd++) {
        const float4* src = (const float4*)(g_h + (size_t)(dd * SS + t) * HH * BB);
        float4* dst = (float4*)(hb + (size_t)dd * HH * BB);
        for (int i = tid; i < 2048; i += 256) dst[i] = src[i];
    }
    __syncthreads();
    for (int o = tid; o < BB * NT; o += 256) {
        int tag = o >> 5;
        int b = o & 31;
        float acc = btag[tag];
        const float* wr = Wtag + (size_t)tag * (2 * HH);
#pragma unroll 8
        for (int k = 0; k < 2 * HH; k++) acc += hb[k * BB + b] * wr[k];
        g_logits[((size_t)b * SS + t) * NT + tag] = acc;
    }
}

// ---------------- CRF forward (NLL per batch) ----------------
__global__ void crf_kernel(const int* __restrict__ mask, const int* __restrict__ labels,
                           const float* __restrict__ trans) {
    __shared__ float tr[NT * NT];
    __shared__ float alpha[NT];
    int b = blockIdx.x, j = threadIdx.x;
    for (int i = j; i < NT * NT; i += 32) tr[i] = trans[i];
    __syncthreads();
    if (j < NT) alpha[j] = g_logits[((size_t)b * SS) * NT + j] + tr[TSTART * NT + j];
    __syncthreads();
    for (int t = 1; t < SS; t++) {
        int mt = mask[b * SS + t];
        float nv = 0.0f;
        if (j < NT) {
            float mx = -1e30f;
#pragma unroll
            for (int i = 0; i < NT; i++) mx = fmaxf(mx, alpha[i] + tr[i * NT + j]);
            float sum = 0.0f;
#pragma unroll
            for (int i = 0; i < NT; i++) sum += expf(alpha[i] + tr[i * NT + j] - mx);
            nv = mx + logf(sum) + g_logits[((size_t)b * SS + t) * NT + j];
        }
        __syncthreads();
        if (j < NT && mt > 0) alpha[j] = nv;
        __syncthreads();
    }
    if (j == 0) {
        float mx = -1e30f;
        for (int i = 0; i < NT; i++) mx = fmaxf(mx, alpha[i] + tr[i * NT + TSTOP]);
        float sum = 0.0f;
        for (int i = 0; i < NT; i++) sum += expf(alpha[i] + tr[i * NT + TSTOP] - mx);
        float logZ = mx + logf(sum);
        float gold = 0.0f;
        int prev = TSTART, len = 0;
        for (int t = 0; t < SS; t++) {
            int lab = labels[b * SS + t];
            if (mask[b * SS + t] > 0) {
                gold += tr[prev * NT + lab] + g_logits[((size_t)b * SS + t) * NT + lab];
                len++;
            }
            prev = lab;
        }
        int last = labels[b * SS + len - 1];
        gold += tr[last * NT + TSTOP];
        g_nll[b] = logZ - gold;
    }
}

// ---------------- Viterbi decode ----------------
__global__ void viterbi_kernel(const int* __restrict__ mask, const float* __restrict__ trans,
                               float* __restrict__ out) {
    __shared__ float tr[NT * NT];
    __shared__ float delta[NT];
    int b = blockIdx.x, j = threadIdx.x;
    for (int i = j; i < NT * NT; i += 32) tr[i] = trans[i];
    __syncthreads();
    if (j < NT) delta[j] = g_logits[((size_t)b * SS) * NT + j] + tr[TSTART * NT + j];
    __syncthreads();
    for (int t = 1; t < SS; t++) {
        int mt = mask[b * SS + t];
        float nv = 0.0f;
        int arg = j;
        if (j < NT) {
            float best = -1e30f;
            int bi = 0;
#pragma unroll
            for (int i = 0; i < NT; i++) {
                float v = delta[i] + tr[i * NT + j];
                if (v > best) { best = v; bi = i; }  // strict '>' => first max (jnp.argmax)
            }
            nv = best + g_logits[((size_t)b * SS + t) * NT + j];
            if (mt > 0) arg = bi;
        }
        __syncthreads();
        if (j < NT) {
            if (mt > 0) delta[j] = nv;
            g_ptr[((size_t)b * SS + t) * NT + j] = arg;
        }
        __syncthreads();
    }
    if (j == 0) {
        float best = -1e30f;
        int bl = 0;
        for (int i = 0; i < NT; i++) {
            float v = delta[i] + tr[i * NT + TSTOP];
            if (v > best) { best = v; bl = i; }
        }
        int tag = bl;
        for (int t = SS - 1; t >= 1; t--) {
            out[1 + b * SS + t] = (float)(mask[b * SS + t] > 0 ? tag : 0);
            tag = g_ptr[((size_t)b * SS + t) * NT + tag];
        }
        out[1 + b * SS + 0] = (float)(mask[b * SS + 0] > 0 ? tag : 0);
    }
}

__global__ void finalize_kernel(float* out) {
    if (threadIdx.x == 0) {
        float s = 0.0f;
        for (int i = 0; i < BB; i++) s += g_nll[i];
        out[0] = s / (float)BB;
    }
}

extern "C" void kernel_launch(void* const* d_in, const int* in_sizes, int n_in,
                              void* d_out, int out_size) {
    // metadata order: word, mask, labels, labels_token, [data_type], emb, WihF, WhhF,
    // bihF, bhhF, WihB, WhhB, bihB, bhhB, Wtag, btag, trans
    int o = (in_sizes[4] == 1) ? 0 : -1;  // data_type scalar present or dropped
    const int*   word   = (const int*)d_in[0];
    const int*   mask   = (const int*)d_in[1];
    const int*   labels = (const int*)d_in[2];
    const float* emb    = (const float*)d_in[5 + o];
    const float* WihF   = (const float*)d_in[6 + o];
    const float* WhhF   = (const float*)d_in[7 + o];
    const float* bihF   = (const float*)d_in[8 + o];
    const float* bhhF   = (const float*)d_in[9 + o];
    const float* WihB   = (const float*)d_in[10 + o];
    const float* WhhB   = (const float*)d_in[11 + o];
    const float* bihB   = (const float*)d_in[12 + o];
    const float* bhhB   = (const float*)d_in[13 + o];
    const float* Wtag   = (const float*)d_in[14 + o];
    const float* btag   = (const float*)d_in[15 + o];
    const float* trans  = (const float*)d_in[16 + o];
    float* out = (float*)d_out;

    // opt-in to >48KB dynamic smem (host-side, not captured)
    cudaFuncSetAttribute(lstm_kernel, cudaFuncAttributeMaxDynamicSharedMemorySize, 58112);
    cudaFuncSetAttribute(logits_kernel, cudaFuncAttributeMaxDynamicSharedMemorySize, 65536);

    int nz = out_size > SS ? out_size : SS;
    zero_out_kernel<<<(nz + 255) / 256, 256>>>(out, out_size);
    embed_kernel<<<(BB * SS * (EP / 4) + 255) / 256, 256>>>(word, mask, emb);
    {
        dim3 grid(BB * SS / 64, T4H / 64, 2);
        gemm_xg_kernel<<<grid, 256>>>(WihF, WihB, bihF, bhhF, bihB, bhhB);
    }
    lstm_kernel<<<128, 128, 58112>>>(WhhF, WhhB);
    logits_kernel<<<SS, 256, 65536>>>(Wtag, btag);
    crf_kernel<<<BB, 32>>>(mask, labels, trans);
    viterbi_kernel<<<BB, 32>>>(mask, trans, out);
    finalize_kernel<<<1, 32>>>(out);
}